// round 2
// baseline (speedup 1.0000x reference)
#include <cuda_runtime.h>
#include <cstdint>

#define EPS 1e-7f
#define MAX_BLOCKS 2048
#define NTHREADS 256

// Per-block partials (fully overwritten each run -> no init kernel needed).
// .x = mse_sum, .y = iou_sum, .z = bit-cast n_inc
__device__ float4 g_partials[MAX_BLOCKS];
__device__ unsigned int g_count;  // zero-init at load; reset to 0 after each use

__device__ __forceinline__ void process_box(
    const float4& p, const float4& g,
    float& mse_sum, float& iou_sum, unsigned int& n_inc)
{
    // gt corners
    float x_min_t = g.x - g.z * 0.5f;
    float x_max_t = g.x + g.z * 0.5f;
    float y_min_t = g.y - g.w * 0.5f;
    float y_max_t = g.y + g.w * 0.5f;
    // pred corners, clipped to [0,1]
    float x_min_p = fmaxf(p.x - p.z * 0.5f, 0.0f);
    float x_max_p = fminf(p.x + p.z * 0.5f, 1.0f);
    float y_min_p = fmaxf(p.y - p.w * 0.5f, 0.0f);
    float y_max_p = fminf(p.y + p.w * 0.5f, 1.0f);
    // overlap box
    float o0 = fmaxf(x_min_t, x_min_p);
    float o1 = fmaxf(y_min_t, y_min_p);
    float o2 = fminf(x_max_t, x_max_p);
    float o3 = fminf(y_max_t, y_max_p);

    bool incorrect = (o2 < o0) || (o3 < o1);
    if (incorrect) {
        float dx = p.x - g.x, dy = p.y - g.y, dz = p.z - g.z, dw = p.w - g.w;
        mse_sum += dx * dx + dy * dy + dz * dz + dw * dw;
        n_inc++;
    } else {
        float area_p = p.z * p.w;
        float area_g = g.z * g.w;
        float inter = (o2 - o0) * (o3 - o1);
        iou_sum += inter / (area_p + area_g - inter + EPS);
    }
}

__global__ void __launch_bounds__(NTHREADS) iou_fused_kernel(
    const float4* __restrict__ pr,
    const float4* __restrict__ gt,
    int n,
    float* __restrict__ out)
{
    float mse_sum = 0.f;
    float iou_sum = 0.f;
    unsigned int n_inc = 0;

    const int stride = gridDim.x * blockDim.x;
    int i = blockIdx.x * blockDim.x + threadIdx.x;

    // Unroll-4 main loop: 8 independent 128-bit loads batched up front (MLP=8).
    for (; i + 3 * stride < n; i += 4 * stride) {
        float4 p0 = __ldg(&pr[i]);
        float4 p1 = __ldg(&pr[i + stride]);
        float4 p2 = __ldg(&pr[i + 2 * stride]);
        float4 p3 = __ldg(&pr[i + 3 * stride]);
        float4 g0 = __ldg(&gt[i]);
        float4 g1 = __ldg(&gt[i + stride]);
        float4 g2 = __ldg(&gt[i + 2 * stride]);
        float4 g3 = __ldg(&gt[i + 3 * stride]);
        process_box(p0, g0, mse_sum, iou_sum, n_inc);
        process_box(p1, g1, mse_sum, iou_sum, n_inc);
        process_box(p2, g2, mse_sum, iou_sum, n_inc);
        process_box(p3, g3, mse_sum, iou_sum, n_inc);
    }
    for (; i < n; i += stride) {
        float4 p = __ldg(&pr[i]);
        float4 g = __ldg(&gt[i]);
        process_box(p, g, mse_sum, iou_sum, n_inc);
    }

    // ---- block reduction ----
    #pragma unroll
    for (int off = 16; off > 0; off >>= 1) {
        mse_sum += __shfl_down_sync(0xffffffffu, mse_sum, off);
        iou_sum += __shfl_down_sync(0xffffffffu, iou_sum, off);
        n_inc   += __shfl_down_sync(0xffffffffu, n_inc, off);
    }

    __shared__ float s_mse[8], s_iou[8];
    __shared__ unsigned int s_inc[8];
    __shared__ bool s_is_last;
    int lane = threadIdx.x & 31;
    int wid = threadIdx.x >> 5;
    if (lane == 0) {
        s_mse[wid] = mse_sum;
        s_iou[wid] = iou_sum;
        s_inc[wid] = n_inc;
    }
    __syncthreads();
    if (wid == 0) {
        mse_sum = (lane < 8) ? s_mse[lane] : 0.f;
        iou_sum = (lane < 8) ? s_iou[lane] : 0.f;
        n_inc   = (lane < 8) ? s_inc[lane] : 0u;
        #pragma unroll
        for (int off = 4; off > 0; off >>= 1) {
            mse_sum += __shfl_down_sync(0xffu, mse_sum, off);
            iou_sum += __shfl_down_sync(0xffu, iou_sum, off);
            n_inc   += __shfl_down_sync(0xffu, n_inc, off);
        }
        if (lane == 0) {
            g_partials[blockIdx.x] = make_float4(mse_sum, iou_sum, __uint_as_float(n_inc), 0.f);
            __threadfence();
            unsigned int v = atomicAdd(&g_count, 1u);
            s_is_last = (v == gridDim.x - 1);
        }
    }
    __syncthreads();

    // ---- last block finalizes ----
    if (s_is_last) {
        double dmse = 0.0, diou = 0.0;
        unsigned long long dinc = 0ull;
        for (int j = threadIdx.x; j < gridDim.x; j += blockDim.x) {
            float4 v = g_partials[j];
            dmse += (double)v.x;
            diou += (double)v.y;
            dinc += (unsigned long long)__float_as_uint(v.z);
        }
        #pragma unroll
        for (int off = 16; off > 0; off >>= 1) {
            dmse += __shfl_down_sync(0xffffffffu, dmse, off);
            diou += __shfl_down_sync(0xffffffffu, diou, off);
            dinc += __shfl_down_sync(0xffffffffu, dinc, off);
        }
        __shared__ double f_mse[8], f_iou[8];
        __shared__ unsigned long long f_inc[8];
        if (lane == 0) {
            f_mse[wid] = dmse;
            f_iou[wid] = diou;
            f_inc[wid] = dinc;
        }
        __syncthreads();
        if (threadIdx.x == 0) {
            dmse = 0.0; diou = 0.0; dinc = 0ull;
            #pragma unroll
            for (int w = 0; w < 8; w++) {
                dmse += f_mse[w];
                diou += f_iou[w];
                dinc += f_inc[w];
            }
            unsigned long long n_corr = (unsigned long long)n - dinc;

            double denom_mse = (double)(dinc * 4ull > 0ull ? dinc * 4ull : 1ull);
            double mse_mean = dmse / denom_mse;
            double denom_iou = (double)(n_corr > 0ull ? n_corr : 1ull);
            double iou_mean = diou / denom_iou;

            double res_full = iou_mean + (dinc > 0ull ? -mse_mean : 0.0);
            double res = (n_corr > 0ull) ? res_full : -mse_mean;
            out[0] = (float)res;

            g_count = 0u;  // reset for next graph replay
        }
    }
}

extern "C" void kernel_launch(void* const* d_in, const int* in_sizes, int n_in,
                              void* d_out, int out_size) {
    const float4* pr = (const float4*)d_in[0];
    const float4* gt = (const float4*)d_in[1];
    int n = in_sizes[0] / 4;  // boxes

    int blocks = 148 * 8;  // one full wave on GB300 (152 SMs; 148 keeps wave tight)
    if (blocks > MAX_BLOCKS) blocks = MAX_BLOCKS;
    int maxNeeded = (n + NTHREADS - 1) / NTHREADS;
    if (blocks > maxNeeded) blocks = maxNeeded;

    iou_fused_kernel<<<blocks, NTHREADS>>>(pr, gt, n, (float*)d_out);
}

// round 3
// speedup vs baseline: 1.0415x; 1.0415x over previous
#include <cuda_runtime.h>
#include <cstdint>

#define EPS 1e-7f
#define MAX_BLOCKS 4096
#define NTHREADS 256

// Per-block partials (fully overwritten each run -> no init kernel needed).
// .x = mse_sum, .y = iou_sum, .z = n_inc (exact small integer in float)
__device__ float4 g_partials[MAX_BLOCKS];
__device__ unsigned int g_count;  // zero-init at load; reset to 0 after each use

__device__ __forceinline__ void process_box(
    const float4 p, const float4 g,
    float& mse_sum, float& iou_sum, float& n_inc_f)
{
    // gt corners
    float x_min_t = fmaf(g.z, -0.5f, g.x);
    float x_max_t = fmaf(g.z,  0.5f, g.x);
    float y_min_t = fmaf(g.w, -0.5f, g.y);
    float y_max_t = fmaf(g.w,  0.5f, g.y);
    // pred corners, clipped to [0,1]
    float x_min_p = fmaxf(fmaf(p.z, -0.5f, p.x), 0.0f);
    float x_max_p = fminf(fmaf(p.z,  0.5f, p.x), 1.0f);
    float y_min_p = fmaxf(fmaf(p.w, -0.5f, p.y), 0.0f);
    float y_max_p = fminf(fmaf(p.w,  0.5f, p.y), 1.0f);
    // overlap box
    float o0 = fmaxf(x_min_t, x_min_p);
    float o1 = fmaxf(y_min_t, y_min_p);
    float o2 = fminf(x_max_t, x_max_p);
    float o3 = fminf(y_max_t, y_max_p);

    // branchless mask: 1.0 if incorrect (no overlap), else 0.0
    float m = ((o2 < o0) || (o3 < o1)) ? 1.0f : 0.0f;

    // mse contribution (only if incorrect)
    float dx = p.x - g.x, dy = p.y - g.y, dz = p.z - g.z, dw = p.w - g.w;
    float sq = dx * dx + dy * dy + dz * dz + dw * dw;

    // iou contribution (only if correct); inter may be negative for
    // non-overlapping boxes but denominator only grows -> safe division
    float inter = (o2 - o0) * (o3 - o1);
    float uni = p.z * p.w + g.z * g.w - inter + EPS;
    float iou = __fdividef(inter, uni);

    mse_sum = fmaf(m, sq, mse_sum);
    iou_sum = fmaf(1.0f - m, iou, iou_sum);
    n_inc_f += m;
}

__global__ void __launch_bounds__(NTHREADS) iou_fused_kernel(
    const float4* __restrict__ pr,
    const float4* __restrict__ gt,
    int n,
    float* __restrict__ out)
{
    float mse_sum = 0.f;
    float iou_sum = 0.f;
    float n_inc_f = 0.f;

    const int stride = gridDim.x * blockDim.x;
    int i = blockIdx.x * blockDim.x + threadIdx.x;

    // Unroll-2: 4 independent 128-bit loads batched up front.
    for (; i + stride < n; i += 2 * stride) {
        float4 p0 = __ldg(&pr[i]);
        float4 p1 = __ldg(&pr[i + stride]);
        float4 g0 = __ldg(&gt[i]);
        float4 g1 = __ldg(&gt[i + stride]);
        process_box(p0, g0, mse_sum, iou_sum, n_inc_f);
        process_box(p1, g1, mse_sum, iou_sum, n_inc_f);
    }
    if (i < n) {
        float4 p = __ldg(&pr[i]);
        float4 g = __ldg(&gt[i]);
        process_box(p, g, mse_sum, iou_sum, n_inc_f);
    }

    // ---- block reduction ----
    #pragma unroll
    for (int off = 16; off > 0; off >>= 1) {
        mse_sum += __shfl_down_sync(0xffffffffu, mse_sum, off);
        iou_sum += __shfl_down_sync(0xffffffffu, iou_sum, off);
        n_inc_f += __shfl_down_sync(0xffffffffu, n_inc_f, off);
    }

    __shared__ float s_mse[8], s_iou[8], s_inc[8];
    __shared__ bool s_is_last;
    int lane = threadIdx.x & 31;
    int wid = threadIdx.x >> 5;
    if (lane == 0) {
        s_mse[wid] = mse_sum;
        s_iou[wid] = iou_sum;
        s_inc[wid] = n_inc_f;
    }
    __syncthreads();
    if (wid == 0) {
        mse_sum = (lane < 8) ? s_mse[lane] : 0.f;
        iou_sum = (lane < 8) ? s_iou[lane] : 0.f;
        n_inc_f = (lane < 8) ? s_inc[lane] : 0.f;
        #pragma unroll
        for (int off = 4; off > 0; off >>= 1) {
            mse_sum += __shfl_down_sync(0xffu, mse_sum, off);
            iou_sum += __shfl_down_sync(0xffu, iou_sum, off);
            n_inc_f += __shfl_down_sync(0xffu, n_inc_f, off);
        }
        if (lane == 0) {
            g_partials[blockIdx.x] = make_float4(mse_sum, iou_sum, n_inc_f, 0.f);
            __threadfence();
            unsigned int v = atomicAdd(&g_count, 1u);
            s_is_last = (v == gridDim.x - 1);
        }
    }
    __syncthreads();

    // ---- last block finalizes ----
    if (s_is_last) {
        double dmse = 0.0, diou = 0.0, dinc_d = 0.0;
        for (int j = threadIdx.x; j < gridDim.x; j += blockDim.x) {
            float4 v = g_partials[j];
            dmse += (double)v.x;
            diou += (double)v.y;
            dinc_d += (double)v.z;
        }
        #pragma unroll
        for (int off = 16; off > 0; off >>= 1) {
            dmse += __shfl_down_sync(0xffffffffu, dmse, off);
            diou += __shfl_down_sync(0xffffffffu, diou, off);
            dinc_d += __shfl_down_sync(0xffffffffu, dinc_d, off);
        }
        __shared__ double f_mse[8], f_iou[8], f_inc[8];
        if (lane == 0) {
            f_mse[wid] = dmse;
            f_iou[wid] = diou;
            f_inc[wid] = dinc_d;
        }
        __syncthreads();
        if (threadIdx.x == 0) {
            dmse = 0.0; diou = 0.0; dinc_d = 0.0;
            #pragma unroll
            for (int w = 0; w < 8; w++) {
                dmse += f_mse[w];
                diou += f_iou[w];
                dinc_d += f_inc[w];
            }
            unsigned long long dinc = (unsigned long long)(dinc_d + 0.5);
            unsigned long long n_corr = (unsigned long long)n - dinc;

            double denom_mse = (double)(dinc * 4ull > 0ull ? dinc * 4ull : 1ull);
            double mse_mean = dmse / denom_mse;
            double denom_iou = (double)(n_corr > 0ull ? n_corr : 1ull);
            double iou_mean = diou / denom_iou;

            double res_full = iou_mean + (dinc > 0ull ? -mse_mean : 0.0);
            double res = (n_corr > 0ull) ? res_full : -mse_mean;
            out[0] = (float)res;

            g_count = 0u;  // reset for next graph replay
        }
    }
}

extern "C" void kernel_launch(void* const* d_in, const int* in_sizes, int n_in,
                              void* d_out, int out_size) {
    const float4* pr = (const float4*)d_in[0];
    const float4* gt = (const float4*)d_in[1];
    int n = in_sizes[0] / 4;  // boxes

    int blocks = 1776;  // 148 SMs x 12; grid-stride evens out waves
    if (blocks > MAX_BLOCKS) blocks = MAX_BLOCKS;
    int maxNeeded = (n + NTHREADS - 1) / NTHREADS;
    if (blocks > maxNeeded) blocks = maxNeeded;

    iou_fused_kernel<<<blocks, NTHREADS>>>(pr, gt, n, (float*)d_out);
}

// round 4
// speedup vs baseline: 1.0782x; 1.0353x over previous
#include <cuda_runtime.h>
#include <cstdint>

#define EPS 1e-7f
#define MAX_BLOCKS 4096
#define NTHREADS 256

// Per-block partials (fully overwritten each run -> no init kernel needed).
// .x = mse_sum, .y = iou_sum, .z = n_inc (exact small integer in float)
__device__ float4 g_partials[MAX_BLOCKS];
__device__ unsigned int g_count;  // zero-init at load; reset to 0 after each use

__device__ __forceinline__ void process_box(
    const float4 p, const float4 g,
    float& mse_sum, float& iou_sum, float& n_inc_f)
{
    // gt corners
    float x_min_t = fmaf(g.z, -0.5f, g.x);
    float x_max_t = fmaf(g.z,  0.5f, g.x);
    float y_min_t = fmaf(g.w, -0.5f, g.y);
    float y_max_t = fmaf(g.w,  0.5f, g.y);
    // pred corners, clipped to [0,1]
    float x_min_p = fmaxf(fmaf(p.z, -0.5f, p.x), 0.0f);
    float x_max_p = fminf(fmaf(p.z,  0.5f, p.x), 1.0f);
    float y_min_p = fmaxf(fmaf(p.w, -0.5f, p.y), 0.0f);
    float y_max_p = fminf(fmaf(p.w,  0.5f, p.y), 1.0f);
    // overlap box
    float o0 = fmaxf(x_min_t, x_min_p);
    float o1 = fmaxf(y_min_t, y_min_p);
    float o2 = fminf(x_max_t, x_max_p);
    float o3 = fminf(y_max_t, y_max_p);

    // branchless mask: 1.0 if incorrect (no overlap), else 0.0
    float m = ((o2 < o0) || (o3 < o1)) ? 1.0f : 0.0f;

    // mse contribution (only if incorrect)
    float dx = p.x - g.x, dy = p.y - g.y, dz = p.z - g.z, dw = p.w - g.w;
    float sq = dx * dx + dy * dy + dz * dz + dw * dw;

    // iou contribution (only if correct); inter may be negative for
    // non-overlapping boxes but denominator only grows -> safe division
    float inter = (o2 - o0) * (o3 - o1);
    float uni = p.z * p.w + g.z * g.w - inter + EPS;
    float iou = __fdividef(inter, uni);

    mse_sum = fmaf(m, sq, mse_sum);
    iou_sum = fmaf(1.0f - m, iou, iou_sum);
    n_inc_f += m;
}

__global__ void __launch_bounds__(NTHREADS) iou_fused_kernel(
    const float4* __restrict__ pr,
    const float4* __restrict__ gt,
    int n,
    float* __restrict__ out)
{
    float mse_sum = 0.f;
    float iou_sum = 0.f;
    float n_inc_f = 0.f;

    const int stride = gridDim.x * blockDim.x;

    // Simple grid-stride loop: warp-level parallelism supplies the MLP;
    // per-thread load batching measurably hurt (R2/R3).
    for (int i = blockIdx.x * blockDim.x + threadIdx.x; i < n; i += stride) {
        float4 p = __ldcs(&pr[i]);   // streaming: zero reuse, don't fight for L2
        float4 g = __ldcs(&gt[i]);
        process_box(p, g, mse_sum, iou_sum, n_inc_f);
    }

    // ---- block reduction ----
    #pragma unroll
    for (int off = 16; off > 0; off >>= 1) {
        mse_sum += __shfl_down_sync(0xffffffffu, mse_sum, off);
        iou_sum += __shfl_down_sync(0xffffffffu, iou_sum, off);
        n_inc_f += __shfl_down_sync(0xffffffffu, n_inc_f, off);
    }

    __shared__ float s_mse[8], s_iou[8], s_inc[8];
    __shared__ bool s_is_last;
    int lane = threadIdx.x & 31;
    int wid = threadIdx.x >> 5;
    if (lane == 0) {
        s_mse[wid] = mse_sum;
        s_iou[wid] = iou_sum;
        s_inc[wid] = n_inc_f;
    }
    __syncthreads();
    if (wid == 0) {
        mse_sum = (lane < 8) ? s_mse[lane] : 0.f;
        iou_sum = (lane < 8) ? s_iou[lane] : 0.f;
        n_inc_f = (lane < 8) ? s_inc[lane] : 0.f;
        #pragma unroll
        for (int off = 4; off > 0; off >>= 1) {
            mse_sum += __shfl_down_sync(0xffu, mse_sum, off);
            iou_sum += __shfl_down_sync(0xffu, iou_sum, off);
            n_inc_f += __shfl_down_sync(0xffu, n_inc_f, off);
        }
        if (lane == 0) {
            g_partials[blockIdx.x] = make_float4(mse_sum, iou_sum, n_inc_f, 0.f);
            __threadfence();
            unsigned int v = atomicAdd(&g_count, 1u);
            s_is_last = (v == gridDim.x - 1);
        }
    }
    __syncthreads();

    // ---- last block finalizes ----
    if (s_is_last) {
        double dmse = 0.0, diou = 0.0, dinc_d = 0.0;
        for (int j = threadIdx.x; j < gridDim.x; j += blockDim.x) {
            float4 v = g_partials[j];
            dmse += (double)v.x;
            diou += (double)v.y;
            dinc_d += (double)v.z;
        }
        #pragma unroll
        for (int off = 16; off > 0; off >>= 1) {
            dmse += __shfl_down_sync(0xffffffffu, dmse, off);
            diou += __shfl_down_sync(0xffffffffu, diou, off);
            dinc_d += __shfl_down_sync(0xffffffffu, dinc_d, off);
        }
        __shared__ double f_mse[8], f_iou[8], f_inc[8];
        if (lane == 0) {
            f_mse[wid] = dmse;
            f_iou[wid] = diou;
            f_inc[wid] = dinc_d;
        }
        __syncthreads();
        if (threadIdx.x == 0) {
            dmse = 0.0; diou = 0.0; dinc_d = 0.0;
            #pragma unroll
            for (int w = 0; w < 8; w++) {
                dmse += f_mse[w];
                diou += f_iou[w];
                dinc_d += f_inc[w];
            }
            unsigned long long dinc = (unsigned long long)(dinc_d + 0.5);
            unsigned long long n_corr = (unsigned long long)n - dinc;

            double denom_mse = (double)(dinc * 4ull > 0ull ? dinc * 4ull : 1ull);
            double mse_mean = dmse / denom_mse;
            double denom_iou = (double)(n_corr > 0ull ? n_corr : 1ull);
            double iou_mean = diou / denom_iou;

            double res_full = iou_mean + (dinc > 0ull ? -mse_mean : 0.0);
            double res = (n_corr > 0ull) ? res_full : -mse_mean;
            out[0] = (float)res;

            g_count = 0u;  // reset for next graph replay
        }
    }
}

extern "C" void kernel_launch(void* const* d_in, const int* in_sizes, int n_in,
                              void* d_out, int out_size) {
    const float4* pr = (const float4*)d_in[0];
    const float4* gt = (const float4*)d_in[1];
    int n = in_sizes[0] / 4;  // boxes

    int blocks = 2048;  // round-1's winning config
    if (blocks > MAX_BLOCKS) blocks = MAX_BLOCKS;
    int maxNeeded = (n + NTHREADS - 1) / NTHREADS;
    if (blocks > maxNeeded) blocks = maxNeeded;

    iou_fused_kernel<<<blocks, NTHREADS>>>(pr, gt, n, (float*)d_out);
}